// round 1
// baseline (speedup 1.0000x reference)
#include <cuda_runtime.h>
#include <math.h>

#define NBATCH 4
#define TSEQ   2048
#define DMODEL 1024
#define NHEADS 16
#define HDIM   64
#define MROWS  (NBATCH * TSEQ)   // 8192

// Scratch (static device globals — no runtime allocation allowed)
__device__ float g_qkv[(size_t)MROWS * 3 * DMODEL];  // ~100 MB
__device__ float g_y[(size_t)MROWS * DMODEL];        // ~33 MB

// ---------------------------------------------------------------------------
// GEMM: C[M,N] = A[M,K] @ W[K,N] + bias[N]
// Tiles 128x128, K-step 32, 256 threads, 8x8 accumulator per thread.
// As stored transposed with +1 padding (conflict-free scalar broadcast reads).
// ---------------------------------------------------------------------------
__global__ __launch_bounds__(256) void gemm_bias_kernel(
    const float* __restrict__ A, const float* __restrict__ W,
    const float* __restrict__ bias, float* __restrict__ C,
    int M, int N, int K)
{
    __shared__ float As[32][129];
    __shared__ float Bs[32][128];
    const int tid  = threadIdx.x;
    const int row0 = blockIdx.y * 128;
    const int col0 = blockIdx.x * 128;
    const int tx = tid & 15;
    const int ty = tid >> 4;

    float acc[8][8];
#pragma unroll
    for (int i = 0; i < 8; i++)
#pragma unroll
        for (int j = 0; j < 8; j++) acc[i][j] = 0.f;

    for (int k0 = 0; k0 < K; k0 += 32) {
        // A tile 128x32 -> As[k][m] (transposed)
#pragma unroll
        for (int i = 0; i < 4; i++) {
            int idx = tid + i * 256;        // float4 index, 1024 total
            int r = idx >> 3;               // 0..127
            int c = (idx & 7) << 2;         // 0..28
            float4 v = *(const float4*)(A + (size_t)(row0 + r) * K + (k0 + c));
            As[c + 0][r] = v.x; As[c + 1][r] = v.y;
            As[c + 2][r] = v.z; As[c + 3][r] = v.w;
        }
        // B tile 32x128 -> Bs[k][n]
#pragma unroll
        for (int i = 0; i < 4; i++) {
            int idx = tid + i * 256;        // float4 index, 1024 total
            int r = idx >> 5;               // 0..31
            int c = (idx & 31) << 2;        // 0..124
            *(float4*)&Bs[r][c] =
                *(const float4*)(W + (size_t)(k0 + r) * N + (col0 + c));
        }
        __syncthreads();
#pragma unroll
        for (int kk = 0; kk < 32; kk++) {
            float a[8], b[8];
#pragma unroll
            for (int i = 0; i < 8; i++) a[i] = As[kk][ty * 8 + i];
            float4 b0 = *(const float4*)&Bs[kk][tx * 8];
            float4 b1 = *(const float4*)&Bs[kk][tx * 8 + 4];
            b[0]=b0.x; b[1]=b0.y; b[2]=b0.z; b[3]=b0.w;
            b[4]=b1.x; b[5]=b1.y; b[6]=b1.z; b[7]=b1.w;
#pragma unroll
            for (int i = 0; i < 8; i++)
#pragma unroll
                for (int j = 0; j < 8; j++)
                    acc[i][j] += a[i] * b[j];
        }
        __syncthreads();
    }

#pragma unroll
    for (int i = 0; i < 8; i++) {
        int r = row0 + ty * 8 + i;
#pragma unroll
        for (int j = 0; j < 8; j += 4) {
            int c = col0 + tx * 8 + j;
            float4 v;
            v.x = acc[i][j + 0] + bias[c + 0];
            v.y = acc[i][j + 1] + bias[c + 1];
            v.z = acc[i][j + 2] + bias[c + 2];
            v.w = acc[i][j + 3] + bias[c + 3];
            *(float4*)(C + (size_t)r * N + c) = v;
        }
    }
}

// ---------------------------------------------------------------------------
// Flash attention (causal), fp32.
// Grid: (TSEQ/128, NBATCH*NHEADS). 128 threads; each thread owns one query
// row: q[64] and o[64] in registers, online softmax. K/V tiles (64x64) in
// SMEM; all inner-loop SMEM reads are warp-broadcast (conflict-free).
// qkv layout: [b, t, 3*D] with q at +0, k at +D, v at +2D, head h at h*HDIM.
// ---------------------------------------------------------------------------
#define ATT_BM 128
#define ATT_BN 64

__global__ __launch_bounds__(ATT_BM) void attn_kernel(
    const float* __restrict__ qkv, float* __restrict__ y)
{
    const int qb  = blockIdx.x;
    const int bh  = blockIdx.y;
    const int b   = bh / NHEADS;
    const int h   = bh % NHEADS;
    const int tid = threadIdx.x;
    const int qi  = qb * ATT_BM + tid;          // global query index in [0,T)

    const float* base = qkv + (size_t)b * TSEQ * 3 * DMODEL;

    __shared__ float Ks[ATT_BN][HDIM];
    __shared__ float Vs[ATT_BN][HDIM];

    // q row -> registers
    float q[HDIM];
    {
        const float* qrow = base + (size_t)qi * 3 * DMODEL + h * HDIM;
#pragma unroll
        for (int c = 0; c < HDIM; c += 4) {
            float4 v = *(const float4*)(qrow + c);
            q[c] = v.x; q[c + 1] = v.y; q[c + 2] = v.z; q[c + 3] = v.w;
        }
    }

    float o[HDIM];
#pragma unroll
    for (int c = 0; c < HDIM; c++) o[c] = 0.f;
    float m = -1e30f, l = 0.f;
    const float scale = 0.125f;                 // 1/sqrt(64)

    const int kend = (qb + 1) * ATT_BM;         // max key needed (exclusive)
    for (int k0 = 0; k0 < kend; k0 += ATT_BN) {
        __syncthreads();   // protect prior-iteration tile reads
        // cooperative K/V tile load: 64x64 floats each = 8 float4 per thread
#pragma unroll
        for (int i = 0; i < 8; i++) {
            int idx = tid + i * ATT_BM;         // float4 index, 1024 total
            int r = idx >> 4;                   // 0..63
            int c = (idx & 15) << 2;            // 0..60
            const float* krow = base + (size_t)(k0 + r) * 3 * DMODEL + DMODEL + h * HDIM;
            const float* vrow = krow + DMODEL;
            float4 kv = *(const float4*)(krow + c);
            Ks[r][c] = kv.x; Ks[r][c+1] = kv.y; Ks[r][c+2] = kv.z; Ks[r][c+3] = kv.w;
            float4 vv = *(const float4*)(vrow + c);
            Vs[r][c] = vv.x; Vs[r][c+1] = vv.y; Vs[r][c+2] = vv.z; Vs[r][c+3] = vv.w;
        }
        __syncthreads();

        // scores for this tile (4-way split accumulators for ILP)
        float p[ATT_BN];
        float tmax = -1e30f;
        for (int j = 0; j < ATT_BN; j++) {
            float s0 = 0.f, s1 = 0.f, s2 = 0.f, s3 = 0.f;
#pragma unroll
            for (int c = 0; c < HDIM; c += 4) {
                float4 kk4 = *(const float4*)&Ks[j][c];   // broadcast
                s0 += q[c + 0] * kk4.x;
                s1 += q[c + 1] * kk4.y;
                s2 += q[c + 2] * kk4.z;
                s3 += q[c + 3] * kk4.w;
            }
            float s = ((s0 + s1) + (s2 + s3)) * scale;
            if (k0 + j > qi) s = -1e30f;                  // causal mask
            p[j] = s;
            tmax = fmaxf(tmax, s);
        }

        float mnew = fmaxf(m, tmax);
        float corr = __expf(m - mnew);
        l *= corr;
#pragma unroll
        for (int c = 0; c < HDIM; c++) o[c] *= corr;
        m = mnew;

        for (int j = 0; j < ATT_BN; j++) {
            float pj = __expf(p[j] - m);
            l += pj;
#pragma unroll
            for (int c = 0; c < HDIM; c += 4) {
                float4 vv4 = *(const float4*)&Vs[j][c];   // broadcast
                o[c + 0] += pj * vv4.x;
                o[c + 1] += pj * vv4.y;
                o[c + 2] += pj * vv4.z;
                o[c + 3] += pj * vv4.w;
            }
        }
    }

    const float inv = 1.f / l;
    float* yrow = y + ((size_t)(b * TSEQ + qi)) * DMODEL + h * HDIM;
#pragma unroll
    for (int c = 0; c < HDIM; c += 4) {
        float4 v;
        v.x = o[c + 0] * inv; v.y = o[c + 1] * inv;
        v.z = o[c + 2] * inv; v.w = o[c + 3] * inv;
        *(float4*)(yrow + c) = v;
    }
}

// ---------------------------------------------------------------------------
extern "C" void kernel_launch(void* const* d_in, const int* in_sizes, int n_in,
                              void* d_out, int out_size)
{
    (void)in_sizes; (void)n_in; (void)out_size;
    const float* x     = (const float*)d_in[0];
    const float* qkv_w = (const float*)d_in[1];
    const float* qkv_b = (const float*)d_in[2];
    const float* o_w   = (const float*)d_in[3];
    const float* o_b   = (const float*)d_in[4];
    float* out = (float*)d_out;

    float* qkv = nullptr;
    float* y   = nullptr;
    cudaGetSymbolAddress((void**)&qkv, g_qkv);
    cudaGetSymbolAddress((void**)&y, g_y);

    // 1) QKV projection: [8192,1024] @ [1024,3072] + bias
    dim3 g1(3 * DMODEL / 128, MROWS / 128);
    gemm_bias_kernel<<<g1, 256>>>(x, qkv_w, qkv_b, qkv, MROWS, 3 * DMODEL, DMODEL);

    // 2) Causal flash attention, per (batch, head)
    dim3 g2(TSEQ / ATT_BM, NBATCH * NHEADS);
    attn_kernel<<<g2, ATT_BM>>>(qkv, y);

    // 3) Output projection: [8192,1024] @ [1024,1024] + bias
    dim3 g3(DMODEL / 128, MROWS / 128);
    gemm_bias_kernel<<<g3, 256>>>(y, o_w, o_b, out, MROWS, DMODEL, DMODEL);
}

// round 3
// speedup vs baseline: 1.3350x; 1.3350x over previous
#include <cuda_runtime.h>
#include <cstdint>
#include <math.h>

#define NBATCH 4
#define TSEQ   2048
#define DMODEL 1024
#define NHEADS 16
#define HDIM   64
#define MROWS  (NBATCH * TSEQ)   // 8192
#define KDIM   DMODEL            // 1024

// ---------------- scratch (static device globals; no runtime alloc) --------
__device__ __align__(1024) float g_qkv[(size_t)MROWS * 3 * DMODEL];   // 100 MB
__device__ __align__(1024) float g_y[(size_t)MROWS * DMODEL];         // 33 MB
__device__ __align__(1024) float g_xr[(size_t)MROWS * DMODEL];        // 33 MB
__device__ __align__(1024) float g_wqkvt[(size_t)3 * DMODEL * DMODEL];// 12 MB
__device__ __align__(1024) float g_wot[(size_t)DMODEL * DMODEL];      // 4 MB

// ---------------- helpers ---------------------------------------------------
__device__ __forceinline__ float tf32r(float x) {
    float r;
    asm("cvt.rna.tf32.f32 %0, %1;" : "=f"(r) : "f"(x));
    return r;
}

#define CP_ASYNC16(dst, src) \
    asm volatile("cp.async.cg.shared.global [%0], [%1], 16;" \
                 :: "r"(dst), "l"(src) : "memory")
#define CP_COMMIT() asm volatile("cp.async.commit_group;" ::: "memory")
#define CP_WAIT1()  asm volatile("cp.async.wait_group 1;" ::: "memory")

__device__ __forceinline__ uint32_t smem_u32(const void* p) {
    uint32_t a;
    asm("{ .reg .u64 t; cvta.to.shared.u64 t, %1; cvt.u32.u64 %0, t; }"
        : "=r"(a) : "l"(p));
    return a;
}

// m16n8k8 tf32 mma: D += A*B.  a:4regs, b:2regs, d:4 fp32.
#define MMA_TF32(d, a, b) \
    asm volatile("mma.sync.aligned.m16n8k8.row.col.f32.tf32.tf32.f32 " \
        "{%0,%1,%2,%3}, {%4,%5,%6,%7}, {%8,%9}, {%0,%1,%2,%3};" \
        : "+f"((d)[0]), "+f"((d)[1]), "+f"((d)[2]), "+f"((d)[3]) \
        : "r"((a)[0]), "r"((a)[1]), "r"((a)[2]), "r"((a)[3]), \
          "r"((b)[0]), "r"((b)[1]))

// ---------------- prep kernels ---------------------------------------------
__global__ void round_tf32_kernel(const float* __restrict__ in,
                                  float* __restrict__ out, int n4) {
    for (int i = blockIdx.x * blockDim.x + threadIdx.x; i < n4;
         i += gridDim.x * blockDim.x) {
        float4 v = *(const float4*)(in + (size_t)i * 4);
        v.x = tf32r(v.x); v.y = tf32r(v.y); v.z = tf32r(v.z); v.w = tf32r(v.w);
        *(float4*)(out + (size_t)i * 4) = v;
    }
}

// W[K,N] -> Wt[N,K] with RNA-tf32 rounding. Block (32,8), tile 32x32.
__global__ void transpose_round_kernel(const float* __restrict__ W,
                                       float* __restrict__ Wt, int K, int N) {
    __shared__ float t[32][33];
    int n0 = blockIdx.x * 32, k0 = blockIdx.y * 32;
    int x = threadIdx.x, y = threadIdx.y;
#pragma unroll
    for (int i = 0; i < 32; i += 8)
        t[y + i][x] = W[(size_t)(k0 + y + i) * N + n0 + x];
    __syncthreads();
#pragma unroll
    for (int i = 0; i < 32; i += 8)
        Wt[(size_t)(n0 + y + i) * K + k0 + x] = tf32r(t[x][y + i]);
}

// ---------------- mma.sync tf32 GEMM ---------------------------------------
// C[M,N] = A[M,K] @ Bt[N,K]^T + bias.  K=1024.  CTA tile 128x128, BK=32,
// 256 threads (8 warps, 4x2), 3-stage cp.async pipeline.
// SMEM pitch 36 floats -> fragment LDS bank = (4*gid + tig) mod 32: conflict-free.
#define GBM 128
#define GBN 128
#define GBK 32
#define GPITCH 36
#define GSTAGES 3
#define TILE_FLOATS (128 * GPITCH)                    // per A or B tile
#define STAGE_FLOATS (2 * TILE_FLOATS)
#define GEMM_SMEM_BYTES (GSTAGES * STAGE_FLOATS * 4)  // 110592
#define GCHUNKS (KDIM / GBK)                          // 32

__global__ __launch_bounds__(256, 1) void gemm_mma_kernel(
    const float* __restrict__ A, const float* __restrict__ Bt,
    const float* __restrict__ bias, float* __restrict__ C, int N)
{
    extern __shared__ float smem[];   // [GSTAGES][2][128][GPITCH]
    const int tid = threadIdx.x;
    const int wid = tid >> 5;
    const int lane = tid & 31;
    const int gid = lane >> 2;        // group id (row within fragment)
    const int tig = lane & 3;         // thread-in-group (col within fragment)

    const size_t row0 = (size_t)blockIdx.y * GBM;
    const size_t col0 = (size_t)blockIdx.x * GBN;
    const int wm0 = (wid & 3) * 32;   // warp m offset in tile
    const int wn0 = (wid >> 2) * 64;  // warp n offset in tile

    const float* Ab = A  + row0 * KDIM;
    const float* Bb = Bt + col0 * KDIM;

    // accumulators: 2 m-tiles x 8 n-tiles x 4 regs
    float acc[2][8][4];
#pragma unroll
    for (int mt = 0; mt < 2; mt++)
#pragma unroll
        for (int nt = 0; nt < 8; nt++)
#pragma unroll
            for (int j = 0; j < 4; j++) acc[mt][nt][j] = 0.f;

    const uint32_t sbase = smem_u32(smem);

    // stage loader: 128 rows x 32 floats for A and B each (256 thr x 4 f4 each)
    auto load_stage = [&](int s, int chunk) {
        const int kof = chunk * GBK;
        uint32_t aS = sbase + (uint32_t)(s * STAGE_FLOATS) * 4u;
        uint32_t bS = aS + (uint32_t)TILE_FLOATS * 4u;
#pragma unroll
        for (int i = 0; i < 4; i++) {
            int idx = tid + i * 256;          // float4 idx, 1024 total
            int r = idx >> 3, c = (idx & 7) << 2;
            uint32_t doff = (uint32_t)(r * GPITCH + c) * 4u;
            CP_ASYNC16(aS + doff, Ab + (size_t)r * KDIM + kof + c);
            CP_ASYNC16(bS + doff, Bb + (size_t)r * KDIM + kof + c);
        }
    };

    load_stage(0, 0); CP_COMMIT();
    load_stage(1, 1); CP_COMMIT();

    for (int c = 0; c < GCHUNKS; c++) {
        CP_WAIT1();
        __syncthreads();
        if (c + 2 < GCHUNKS) load_stage((c + 2) % GSTAGES, c + 2);
        CP_COMMIT();

        const float* As = smem + (c % GSTAGES) * STAGE_FLOATS;
        const float* Bs = As + TILE_FLOATS;
#pragma unroll
        for (int kk = 0; kk < 4; kk++) {
            const int kb = kk * 8;
            uint32_t a[2][4];
#pragma unroll
            for (int mt = 0; mt < 2; mt++) {
                int r = wm0 + mt * 16 + gid;
                a[mt][0] = __float_as_uint(As[(r    ) * GPITCH + kb + tig    ]);
                a[mt][1] = __float_as_uint(As[(r + 8) * GPITCH + kb + tig    ]);
                a[mt][2] = __float_as_uint(As[(r    ) * GPITCH + kb + tig + 4]);
                a[mt][3] = __float_as_uint(As[(r + 8) * GPITCH + kb + tig + 4]);
            }
            uint32_t b[8][2];
#pragma unroll
            for (int nt = 0; nt < 8; nt++) {
                int n = wn0 + nt * 8 + gid;
                b[nt][0] = __float_as_uint(Bs[n * GPITCH + kb + tig    ]);
                b[nt][1] = __float_as_uint(Bs[n * GPITCH + kb + tig + 4]);
            }
#pragma unroll
            for (int mt = 0; mt < 2; mt++)
#pragma unroll
                for (int nt = 0; nt < 8; nt++)
                    MMA_TF32(acc[mt][nt], a[mt], b[nt]);
        }
        __syncthreads();
    }

    // epilogue: bias + store (c0,c1 at row r, c2,c3 at row r+8)
#pragma unroll
    for (int mt = 0; mt < 2; mt++) {
        size_t r = row0 + wm0 + mt * 16 + gid;
#pragma unroll
        for (int nt = 0; nt < 8; nt++) {
            size_t col = col0 + wn0 + nt * 8 + tig * 2;
            float2 bb = *(const float2*)(bias + col);
            float2 v0 = { acc[mt][nt][0] + bb.x, acc[mt][nt][1] + bb.y };
            float2 v1 = { acc[mt][nt][2] + bb.x, acc[mt][nt][3] + bb.y };
            *(float2*)(C + r * N + col) = v0;
            *(float2*)(C + (r + 8) * N + col) = v1;
        }
    }
}

// ---------------- flash attention (fp32 SIMT) ------------------------------
#define ATT_BM 128
#define ATT_BN 64

__global__ __launch_bounds__(ATT_BM) void attn_kernel(
    const float* __restrict__ qkv, float* __restrict__ y)
{
    const int qb  = blockIdx.x;
    const int bh  = blockIdx.y;
    const int b   = bh / NHEADS;
    const int h   = bh % NHEADS;
    const int tid = threadIdx.x;
    const int qi  = qb * ATT_BM + tid;

    const float* base = qkv + (size_t)b * TSEQ * 3 * DMODEL;

    __shared__ float Ks[ATT_BN][HDIM];
    __shared__ float Vs[ATT_BN][HDIM];

    float q[HDIM];
    {
        const float* qrow = base + (size_t)qi * 3 * DMODEL + h * HDIM;
#pragma unroll
        for (int c = 0; c < HDIM; c += 4) {
            float4 v = *(const float4*)(qrow + c);
            q[c] = v.x; q[c + 1] = v.y; q[c + 2] = v.z; q[c + 3] = v.w;
        }
    }

    float o[HDIM];
#pragma unroll
    for (int c = 0; c < HDIM; c++) o[c] = 0.f;
    float m = -1e30f, l = 0.f;
    const float scale = 0.125f;

    const int kend = (qb + 1) * ATT_BM;
    for (int k0 = 0; k0 < kend; k0 += ATT_BN) {
        __syncthreads();
#pragma unroll
        for (int i = 0; i < 8; i++) {
            int idx = tid + i * ATT_BM;
            int r = idx >> 4;
            int c = (idx & 15) << 2;
            const float* krow = base + (size_t)(k0 + r) * 3 * DMODEL + DMODEL + h * HDIM;
            const float* vrow = krow + DMODEL;
            float4 kv = *(const float4*)(krow + c);
            Ks[r][c] = kv.x; Ks[r][c+1] = kv.y; Ks[r][c+2] = kv.z; Ks[r][c+3] = kv.w;
            float4 vv = *(const float4*)(vrow + c);
            Vs[r][c] = vv.x; Vs[r][c+1] = vv.y; Vs[r][c+2] = vv.z; Vs[r][c+3] = vv.w;
        }
        __syncthreads();

        float p[ATT_BN];
        float tmax = -1e30f;
        for (int j = 0; j < ATT_BN; j++) {
            float s0 = 0.f, s1 = 0.f, s2 = 0.f, s3 = 0.f;
#pragma unroll
            for (int c = 0; c < HDIM; c += 4) {
                float4 kk4 = *(const float4*)&Ks[j][c];
                s0 += q[c + 0] * kk4.x;
                s1 += q[c + 1] * kk4.y;
                s2 += q[c + 2] * kk4.z;
                s3 += q[c + 3] * kk4.w;
            }
            float s = ((s0 + s1) + (s2 + s3)) * scale;
            if (k0 + j > qi) s = -1e30f;
            p[j] = s;
            tmax = fmaxf(tmax, s);
        }

        float mnew = fmaxf(m, tmax);
        float corr = __expf(m - mnew);
        l *= corr;
#pragma unroll
        for (int c = 0; c < HDIM; c++) o[c] *= corr;
        m = mnew;

        for (int j = 0; j < ATT_BN; j++) {
            float pj = __expf(p[j] - m);
            l += pj;
#pragma unroll
            for (int c = 0; c < HDIM; c += 4) {
                float4 vv4 = *(const float4*)&Vs[j][c];
                o[c + 0] += pj * vv4.x;
                o[c + 1] += pj * vv4.y;
                o[c + 2] += pj * vv4.z;
                o[c + 3] += pj * vv4.w;
            }
        }
    }

    const float inv = 1.f / l;
    float* yrow = y + ((size_t)(b * TSEQ + qi)) * DMODEL + h * HDIM;
#pragma unroll
    for (int c = 0; c < HDIM; c += 4) {
        float4 v;
        v.x = tf32r(o[c + 0] * inv); v.y = tf32r(o[c + 1] * inv);
        v.z = tf32r(o[c + 2] * inv); v.w = tf32r(o[c + 3] * inv);
        *(float4*)(yrow + c) = v;
    }
}

// ---------------------------------------------------------------------------
extern "C" void kernel_launch(void* const* d_in, const int* in_sizes, int n_in,
                              void* d_out, int out_size)
{
    (void)in_sizes; (void)n_in; (void)out_size;
    const float* x     = (const float*)d_in[0];
    const float* qkv_w = (const float*)d_in[1];
    const float* qkv_b = (const float*)d_in[2];
    const float* o_w   = (const float*)d_in[3];
    const float* o_b   = (const float*)d_in[4];
    float* out = (float*)d_out;

    float *qkv, *y, *xr, *wqkvt, *wot;
    cudaGetSymbolAddress((void**)&qkv, g_qkv);
    cudaGetSymbolAddress((void**)&y, g_y);
    cudaGetSymbolAddress((void**)&xr, g_xr);
    cudaGetSymbolAddress((void**)&wqkvt, g_wqkvt);
    cudaGetSymbolAddress((void**)&wot, g_wot);

    cudaFuncSetAttribute(gemm_mma_kernel,
                         cudaFuncAttributeMaxDynamicSharedMemorySize,
                         GEMM_SMEM_BYTES);

    // Pre-round activations; pre-transpose+round weights (tf32 RNA)
    round_tf32_kernel<<<1024, 256>>>(x, xr, MROWS * DMODEL / 4);
    transpose_round_kernel<<<dim3(3 * DMODEL / 32, DMODEL / 32), dim3(32, 8)>>>(
        qkv_w, wqkvt, DMODEL, 3 * DMODEL);
    transpose_round_kernel<<<dim3(DMODEL / 32, DMODEL / 32), dim3(32, 8)>>>(
        o_w, wot, DMODEL, DMODEL);

    // 1) QKV projection (mma.sync tf32): [8192,1024] @ [1024,3072]
    gemm_mma_kernel<<<dim3(3 * DMODEL / GBN, MROWS / GBM), 256, GEMM_SMEM_BYTES>>>(
        xr, wqkvt, qkv_b, qkv, 3 * DMODEL);

    // 2) Causal flash attention (fp32 SIMT)
    attn_kernel<<<dim3(TSEQ / ATT_BM, NBATCH * NHEADS), ATT_BM>>>(qkv, y);

    // 3) Output projection (mma.sync tf32): [8192,1024] @ [1024,1024]
    gemm_mma_kernel<<<dim3(DMODEL / GBN, MROWS / GBM), 256, GEMM_SMEM_BYTES>>>(
        y, wot, o_b, out, DMODEL);
}

// round 5
// speedup vs baseline: 3.2656x; 2.4461x over previous
#include <cuda_runtime.h>
#include <cstdint>
#include <math.h>

#define NBATCH 4
#define TSEQ   2048
#define DMODEL 1024
#define NHEADS 16
#define HDIM   64
#define MROWS  (NBATCH * TSEQ)   // 8192
#define KDIM   DMODEL            // 1024

// ---------------- scratch (static device globals; no runtime alloc) --------
__device__ __align__(1024) float g_qkv[(size_t)MROWS * 3 * DMODEL];   // 100 MB
__device__ __align__(1024) float g_y[(size_t)MROWS * DMODEL];         // 33 MB
__device__ __align__(1024) float g_xr[(size_t)MROWS * DMODEL];        // 33 MB
__device__ __align__(1024) float g_wqkvt[(size_t)3 * DMODEL * DMODEL];// 12 MB
__device__ __align__(1024) float g_wot[(size_t)DMODEL * DMODEL];      // 4 MB

// ---------------- helpers ---------------------------------------------------
__device__ __forceinline__ float tf32r(float x) {
    float r;
    asm("cvt.rna.tf32.f32 %0, %1;" : "=f"(r) : "f"(x));
    return r;
}

#define CP_ASYNC16(dst, src) \
    asm volatile("cp.async.cg.shared.global [%0], [%1], 16;" \
                 :: "r"(dst), "l"(src) : "memory")
#define CP_COMMIT() asm volatile("cp.async.commit_group;" ::: "memory")
#define CP_WAIT1()  asm volatile("cp.async.wait_group 1;" ::: "memory")

__device__ __forceinline__ uint32_t smem_u32(const void* p) {
    uint32_t a;
    asm("{ .reg .u64 t; cvta.to.shared.u64 t, %1; cvt.u32.u64 %0, t; }"
        : "=r"(a) : "l"(p));
    return a;
}

// m16n8k8 tf32 mma: D += A*B.  a:4regs, b:2regs, d:4 fp32.
#define MMA_TF32(d, a, b) \
    asm volatile("mma.sync.aligned.m16n8k8.row.col.f32.tf32.tf32.f32 " \
        "{%0,%1,%2,%3}, {%4,%5,%6,%7}, {%8,%9}, {%0,%1,%2,%3};" \
        : "+f"((d)[0]), "+f"((d)[1]), "+f"((d)[2]), "+f"((d)[3]) \
        : "r"((a)[0]), "r"((a)[1]), "r"((a)[2]), "r"((a)[3]), \
          "r"((b)[0]), "r"((b)[1]))

// ---------------- prep kernels ---------------------------------------------
__global__ void round_tf32_kernel(const float* __restrict__ in,
                                  float* __restrict__ out, int n4) {
    for (int i = blockIdx.x * blockDim.x + threadIdx.x; i < n4;
         i += gridDim.x * blockDim.x) {
        float4 v = *(const float4*)(in + (size_t)i * 4);
        v.x = tf32r(v.x); v.y = tf32r(v.y); v.z = tf32r(v.z); v.w = tf32r(v.w);
        *(float4*)(out + (size_t)i * 4) = v;
    }
}

// W[K,N] -> Wt[N,K] with RNA-tf32 rounding. Block (32,8), tile 32x32.
__global__ void transpose_round_kernel(const float* __restrict__ W,
                                       float* __restrict__ Wt, int K, int N) {
    __shared__ float t[32][33];
    int n0 = blockIdx.x * 32, k0 = blockIdx.y * 32;
    int x = threadIdx.x, y = threadIdx.y;
#pragma unroll
    for (int i = 0; i < 32; i += 8)
        t[y + i][x] = W[(size_t)(k0 + y + i) * N + n0 + x];
    __syncthreads();
#pragma unroll
    for (int i = 0; i < 32; i += 8)
        Wt[(size_t)(n0 + y + i) * K + k0 + x] = tf32r(t[x][y + i]);
}

// ---------------- mma.sync tf32 GEMM (unchanged, R3-validated) -------------
#define GBM 128
#define GBN 128
#define GBK 32
#define GPITCH 36
#define GSTAGES 3
#define TILE_FLOATS (128 * GPITCH)
#define STAGE_FLOATS (2 * TILE_FLOATS)
#define GEMM_SMEM_BYTES (GSTAGES * STAGE_FLOATS * 4)  // 110592
#define GCHUNKS (KDIM / GBK)

__global__ __launch_bounds__(256, 1) void gemm_mma_kernel(
    const float* __restrict__ A, const float* __restrict__ Bt,
    const float* __restrict__ bias, float* __restrict__ C, int N)
{
    extern __shared__ float smem[];
    const int tid = threadIdx.x;
    const int wid = tid >> 5;
    const int lane = tid & 31;
    const int gid = lane >> 2;
    const int tig = lane & 3;

    const size_t row0 = (size_t)blockIdx.y * GBM;
    const size_t col0 = (size_t)blockIdx.x * GBN;
    const int wm0 = (wid & 3) * 32;
    const int wn0 = (wid >> 2) * 64;

    const float* Ab = A  + row0 * KDIM;
    const float* Bb = Bt + col0 * KDIM;

    float acc[2][8][4];
#pragma unroll
    for (int mt = 0; mt < 2; mt++)
#pragma unroll
        for (int nt = 0; nt < 8; nt++)
#pragma unroll
            for (int j = 0; j < 4; j++) acc[mt][nt][j] = 0.f;

    const uint32_t sbase = smem_u32(smem);

    auto load_stage = [&](int s, int chunk) {
        const int kof = chunk * GBK;
        uint32_t aS = sbase + (uint32_t)(s * STAGE_FLOATS) * 4u;
        uint32_t bS = aS + (uint32_t)TILE_FLOATS * 4u;
#pragma unroll
        for (int i = 0; i < 4; i++) {
            int idx = tid + i * 256;
            int r = idx >> 3, c = (idx & 7) << 2;
            uint32_t doff = (uint32_t)(r * GPITCH + c) * 4u;
            CP_ASYNC16(aS + doff, Ab + (size_t)r * KDIM + kof + c);
            CP_ASYNC16(bS + doff, Bb + (size_t)r * KDIM + kof + c);
        }
    };

    load_stage(0, 0); CP_COMMIT();
    load_stage(1, 1); CP_COMMIT();

    for (int c = 0; c < GCHUNKS; c++) {
        CP_WAIT1();
        __syncthreads();
        if (c + 2 < GCHUNKS) load_stage((c + 2) % GSTAGES, c + 2);
        CP_COMMIT();

        const float* As = smem + (c % GSTAGES) * STAGE_FLOATS;
        const float* Bs = As + TILE_FLOATS;
#pragma unroll
        for (int kk = 0; kk < 4; kk++) {
            const int kb = kk * 8;
            uint32_t a[2][4];
#pragma unroll
            for (int mt = 0; mt < 2; mt++) {
                int r = wm0 + mt * 16 + gid;
                a[mt][0] = __float_as_uint(As[(r    ) * GPITCH + kb + tig    ]);
                a[mt][1] = __float_as_uint(As[(r + 8) * GPITCH + kb + tig    ]);
                a[mt][2] = __float_as_uint(As[(r    ) * GPITCH + kb + tig + 4]);
                a[mt][3] = __float_as_uint(As[(r + 8) * GPITCH + kb + tig + 4]);
            }
            uint32_t b[8][2];
#pragma unroll
            for (int nt = 0; nt < 8; nt++) {
                int n = wn0 + nt * 8 + gid;
                b[nt][0] = __float_as_uint(Bs[n * GPITCH + kb + tig    ]);
                b[nt][1] = __float_as_uint(Bs[n * GPITCH + kb + tig + 4]);
            }
#pragma unroll
            for (int mt = 0; mt < 2; mt++)
#pragma unroll
                for (int nt = 0; nt < 8; nt++)
                    MMA_TF32(acc[mt][nt], a[mt], b[nt]);
        }
        __syncthreads();
    }

#pragma unroll
    for (int mt = 0; mt < 2; mt++) {
        size_t r = row0 + wm0 + mt * 16 + gid;
#pragma unroll
        for (int nt = 0; nt < 8; nt++) {
            size_t col = col0 + wn0 + nt * 8 + tig * 2;
            float2 bb = *(const float2*)(bias + col);
            float2 v0 = { acc[mt][nt][0] + bb.x, acc[mt][nt][1] + bb.y };
            float2 v1 = { acc[mt][nt][2] + bb.x, acc[mt][nt][3] + bb.y };
            *(float2*)(C + r * N + col) = v0;
            *(float2*)(C + (r + 8) * N + col) = v1;
        }
    }
}

// ---------------- tensor-core flash attention (tf32 mma.sync) --------------
// Per CTA: one (b, h, 128-q-row tile). 8 warps, warp w owns q rows
// [w*16, w*16+16). Key tiles of 64. S and P@V on m16n8k8 tf32 mma.
// l is accumulated per-thread (16 of the row's 64 cols) and quad-reduced
// at the END (valid because the per-tile rescale c is quad-uniform).
#define ABM 128
#define ABN 64
#define AP  68
#define ATT_SMEM_BYTES ((2 * ABN * AP + ABM * AP) * 4)   // 69632

__global__ __launch_bounds__(256) void attn_mma_kernel(
    const float* __restrict__ qkv, float* __restrict__ y)
{
    extern __shared__ float sm[];
    float* Ks = sm;                  // [64][AP]
    float* Vs = sm + ABN * AP;       // [64][AP]
    float* Ps = sm + 2 * ABN * AP;   // [128][AP]

    const int qb  = gridDim.x - 1 - blockIdx.x;    // big tiles first
    const int bh  = blockIdx.y;
    const int b   = bh >> 4;
    const int h   = bh & 15;
    const int tid = threadIdx.x;
    const int wid = tid >> 5;
    const int lane = tid & 31;
    const int gid = lane >> 2;
    const int tig = lane & 3;
    const int wrow = wid * 16;
    const int q0 = qb * ABM;

    const float* base = qkv + (size_t)b * TSEQ * 3 * DMODEL;

    // ---- stage Q (scaled by 1/8, tf32-rounded) into Ps, pull fragments ----
#pragma unroll
    for (int i = 0; i < 8; i++) {
        int idx = tid + i * 256;
        int r = idx >> 4, c = (idx & 15) << 2;
        float4 v = *(const float4*)(base + (size_t)(q0 + r) * 3 * DMODEL + h * HDIM + c);
        Ps[r * AP + c + 0] = tf32r(v.x * 0.125f);
        Ps[r * AP + c + 1] = tf32r(v.y * 0.125f);
        Ps[r * AP + c + 2] = tf32r(v.z * 0.125f);
        Ps[r * AP + c + 3] = tf32r(v.w * 0.125f);
    }
    __syncthreads();

    uint32_t qf[8][4];
#pragma unroll
    for (int kk = 0; kk < 8; kk++) {
        int kb = kk * 8;
        qf[kk][0] = __float_as_uint(Ps[(wrow + gid    ) * AP + kb + tig    ]);
        qf[kk][1] = __float_as_uint(Ps[(wrow + gid + 8) * AP + kb + tig    ]);
        qf[kk][2] = __float_as_uint(Ps[(wrow + gid    ) * AP + kb + tig + 4]);
        qf[kk][3] = __float_as_uint(Ps[(wrow + gid + 8) * AP + kb + tig + 4]);
    }
    __syncthreads();

    const int r0g = q0 + wrow + gid;
    const int r1g = r0g + 8;

    float m0 = -1e30f, m1 = -1e30f, l0 = 0.f, l1 = 0.f;
    float oacc[8][4];
#pragma unroll
    for (int nt = 0; nt < 8; nt++)
#pragma unroll
        for (int j = 0; j < 4; j++) oacc[nt][j] = 0.f;

    const int ntiles = (qb + 1) * (ABM / ABN);
    for (int t = 0; t < ntiles; t++) {
        const int k0 = t * ABN;
        __syncthreads();
        // ---- cooperative K/V tile load (tf32-rounded) ----
#pragma unroll
        for (int i = 0; i < 4; i++) {
            int idx = tid + i * 256;
            int r = idx >> 4, c = (idx & 15) << 2;
            const float* kr = base + (size_t)(k0 + r) * 3 * DMODEL + DMODEL + h * HDIM + c;
            float4 kv = *(const float4*)kr;
            Ks[r * AP + c + 0] = tf32r(kv.x); Ks[r * AP + c + 1] = tf32r(kv.y);
            Ks[r * AP + c + 2] = tf32r(kv.z); Ks[r * AP + c + 3] = tf32r(kv.w);
            float4 vv = *(const float4*)(kr + DMODEL);
            Vs[r * AP + c + 0] = tf32r(vv.x); Vs[r * AP + c + 1] = tf32r(vv.y);
            Vs[r * AP + c + 2] = tf32r(vv.z); Vs[r * AP + c + 3] = tf32r(vv.w);
        }
        __syncthreads();

        if (k0 > q0 + wrow + 15) continue;          // warp fully masked

        // ---- S = Q @ K^T (scaled already) ----
        float sacc[8][4];
#pragma unroll
        for (int nt = 0; nt < 8; nt++)
#pragma unroll
            for (int j = 0; j < 4; j++) sacc[nt][j] = 0.f;
#pragma unroll
        for (int kk = 0; kk < 8; kk++) {
            int kb = kk * 8;
            uint32_t bf[8][2];
#pragma unroll
            for (int nt = 0; nt < 8; nt++) {
                bf[nt][0] = __float_as_uint(Ks[(nt * 8 + gid) * AP + kb + tig    ]);
                bf[nt][1] = __float_as_uint(Ks[(nt * 8 + gid) * AP + kb + tig + 4]);
            }
#pragma unroll
            for (int nt = 0; nt < 8; nt++)
                MMA_TF32(sacc[nt], qf[kk], bf[nt]);
        }

        // ---- causal mask + quad row max ----
        float tmax0 = -1e30f, tmax1 = -1e30f;
#pragma unroll
        for (int nt = 0; nt < 8; nt++) {
            int col = k0 + nt * 8 + 2 * tig;
            if (col     > r0g) sacc[nt][0] = -1e30f;
            if (col + 1 > r0g) sacc[nt][1] = -1e30f;
            if (col     > r1g) sacc[nt][2] = -1e30f;
            if (col + 1 > r1g) sacc[nt][3] = -1e30f;
            tmax0 = fmaxf(tmax0, fmaxf(sacc[nt][0], sacc[nt][1]));
            tmax1 = fmaxf(tmax1, fmaxf(sacc[nt][2], sacc[nt][3]));
        }
#pragma unroll
        for (int d = 1; d <= 2; d <<= 1) {
            tmax0 = fmaxf(tmax0, __shfl_xor_sync(0xffffffffu, tmax0, d));
            tmax1 = fmaxf(tmax1, __shfl_xor_sync(0xffffffffu, tmax1, d));
        }

        float mn0 = fmaxf(m0, tmax0), mn1 = fmaxf(m1, tmax1);
        float c0 = __expf(m0 - mn0), c1 = __expf(m1 - mn1);
        l0 *= c0; l1 *= c1; m0 = mn0; m1 = mn1;
#pragma unroll
        for (int nt = 0; nt < 8; nt++) {
            oacc[nt][0] *= c0; oacc[nt][1] *= c0;
            oacc[nt][2] *= c1; oacc[nt][3] *= c1;
        }

        // ---- P = exp(S - m); accumulate partial l; store P tile ----
        __syncwarp();
#pragma unroll
        for (int nt = 0; nt < 8; nt++) {
            float p0 = __expf(sacc[nt][0] - m0);
            float p1 = __expf(sacc[nt][1] - m0);
            float p2 = __expf(sacc[nt][2] - m1);
            float p3 = __expf(sacc[nt][3] - m1);
            l0 += p0 + p1; l1 += p2 + p3;
            float2 v01 = { tf32r(p0), tf32r(p1) };
            float2 v23 = { tf32r(p2), tf32r(p3) };
            *(float2*)&Ps[(wrow + gid    ) * AP + nt * 8 + 2 * tig] = v01;
            *(float2*)&Ps[(wrow + gid + 8) * AP + nt * 8 + 2 * tig] = v23;
        }
        __syncwarp();

        // ---- O += P @ V ----
#pragma unroll
        for (int kk = 0; kk < 8; kk++) {
            int kb = kk * 8;
            uint32_t a[4];
            a[0] = __float_as_uint(Ps[(wrow + gid    ) * AP + kb + tig    ]);
            a[1] = __float_as_uint(Ps[(wrow + gid + 8) * AP + kb + tig    ]);
            a[2] = __float_as_uint(Ps[(wrow + gid    ) * AP + kb + tig + 4]);
            a[3] = __float_as_uint(Ps[(wrow + gid + 8) * AP + kb + tig + 4]);
#pragma unroll
            for (int nt = 0; nt < 8; nt++) {
                uint32_t bv[2];
                bv[0] = __float_as_uint(Vs[(kb + tig    ) * AP + nt * 8 + gid]);
                bv[1] = __float_as_uint(Vs[(kb + tig + 4) * AP + nt * 8 + gid]);
                MMA_TF32(oacc[nt], a, bv);
            }
        }
    }

    // ---- FIX: reduce partial row-sums l over the quad (each lane held
    // only 16 of the row's 64 columns; valid post-hoc since every per-tile
    // rescale factor was quad-uniform) ----
#pragma unroll
    for (int d = 1; d <= 2; d <<= 1) {
        l0 += __shfl_xor_sync(0xffffffffu, l0, d);
        l1 += __shfl_xor_sync(0xffffffffu, l1, d);
    }

    // ---- finalize: normalize, tf32-round, store y ----
    float inv0 = 1.f / l0, inv1 = 1.f / l1;
    float* y0 = y + (size_t)(b * TSEQ + r0g) * DMODEL + h * HDIM;
    float* y1 = y + (size_t)(b * TSEQ + r1g) * DMODEL + h * HDIM;
#pragma unroll
    for (int nt = 0; nt < 8; nt++) {
        int col = nt * 8 + 2 * tig;
        float2 v0 = { tf32r(oacc[nt][0] * inv0), tf32r(oacc[nt][1] * inv0) };
        float2 v1 = { tf32r(oacc[nt][2] * inv1), tf32r(oacc[nt][3] * inv1) };
        *(float2*)(y0 + col) = v0;
        *(float2*)(y1 + col) = v1;
    }
}

// ---------------------------------------------------------------------------
extern "C" void kernel_launch(void* const* d_in, const int* in_sizes, int n_in,
                              void* d_out, int out_size)
{
    (void)in_sizes; (void)n_in; (void)out_size;
    const float* x     = (const float*)d_in[0];
    const float* qkv_w = (const float*)d_in[1];
    const float* qkv_b = (const float*)d_in[2];
    const float* o_w   = (const float*)d_in[3];
    const float* o_b   = (const float*)d_in[4];
    float* out = (float*)d_out;

    float *qkv, *y, *xr, *wqkvt, *wot;
    cudaGetSymbolAddress((void**)&qkv, g_qkv);
    cudaGetSymbolAddress((void**)&y, g_y);
    cudaGetSymbolAddress((void**)&xr, g_xr);
    cudaGetSymbolAddress((void**)&wqkvt, g_wqkvt);
    cudaGetSymbolAddress((void**)&wot, g_wot);

    cudaFuncSetAttribute(gemm_mma_kernel,
                         cudaFuncAttributeMaxDynamicSharedMemorySize,
                         GEMM_SMEM_BYTES);
    cudaFuncSetAttribute(attn_mma_kernel,
                         cudaFuncAttributeMaxDynamicSharedMemorySize,
                         ATT_SMEM_BYTES);

    round_tf32_kernel<<<1024, 256>>>(x, xr, MROWS * DMODEL / 4);
    transpose_round_kernel<<<dim3(3 * DMODEL / 32, DMODEL / 32), dim3(32, 8)>>>(
        qkv_w, wqkvt, DMODEL, 3 * DMODEL);
    transpose_round_kernel<<<dim3(DMODEL / 32, DMODEL / 32), dim3(32, 8)>>>(
        o_w, wot, DMODEL, DMODEL);

    // 1) QKV projection (mma.sync tf32)
    gemm_mma_kernel<<<dim3(3 * DMODEL / GBN, MROWS / GBM), 256, GEMM_SMEM_BYTES>>>(
        xr, wqkvt, qkv_b, qkv, 3 * DMODEL);

    // 2) Causal flash attention (mma.sync tf32)
    attn_mma_kernel<<<dim3(TSEQ / ABM, NBATCH * NHEADS), 256, ATT_SMEM_BYTES>>>(
        qkv, y);

    // 3) Output projection (mma.sync tf32)
    gemm_mma_kernel<<<dim3(DMODEL / GBN, MROWS / GBM), 256, GEMM_SMEM_BYTES>>>(
        y, wot, o_b, out, DMODEL);
}

// round 6
// speedup vs baseline: 5.9840x; 1.8324x over previous
#include <cuda_runtime.h>
#include <cuda_fp16.h>
#include <cstdint>
#include <math.h>

#define NBATCH 4
#define TSEQ   2048
#define DMODEL 1024
#define NHEADS 16
#define HDIM   64
#define MROWS  (NBATCH * TSEQ)   // 8192
#define KDIM   DMODEL            // 1024
#define D3     (3 * DMODEL)

// ---------------- scratch (static device globals; no runtime alloc) --------
__device__ __align__(1024) __half g_xh[(size_t)MROWS * DMODEL];        // 16 MB
__device__ __align__(1024) __half g_qkvh[(size_t)MROWS * D3];          // 50 MB
__device__ __align__(1024) __half g_yh[(size_t)MROWS * DMODEL];        // 16 MB
__device__ __align__(1024) __half g_wqkvt[(size_t)D3 * DMODEL];        // 6 MB
__device__ __align__(1024) __half g_wot[(size_t)DMODEL * DMODEL];      // 2 MB

// ---------------- helpers ---------------------------------------------------
#define CP_ASYNC16(dst, src) \
    asm volatile("cp.async.cg.shared.global [%0], [%1], 16;" \
                 :: "r"(dst), "l"(src) : "memory")
#define CP_COMMIT() asm volatile("cp.async.commit_group;" ::: "memory")
#define CP_WAIT2()  asm volatile("cp.async.wait_group 2;" ::: "memory")

__device__ __forceinline__ uint32_t smem_u32(const void* p) {
    uint32_t a;
    asm("{ .reg .u64 t; cvta.to.shared.u64 t, %1; cvt.u32.u64 %0, t; }"
        : "=r"(a) : "l"(p));
    return a;
}

// m16n8k16 fp16 mma, fp32 accum: a:4 b32 regs, b:2, d:4 f32.
#define MMA_F16(d, a, b) \
    asm volatile("mma.sync.aligned.m16n8k16.row.col.f32.f16.f16.f32 " \
        "{%0,%1,%2,%3}, {%4,%5,%6,%7}, {%8,%9}, {%0,%1,%2,%3};" \
        : "+f"((d)[0]), "+f"((d)[1]), "+f"((d)[2]), "+f"((d)[3]) \
        : "r"((a)[0]), "r"((a)[1]), "r"((a)[2]), "r"((a)[3]), \
          "r"((b)[0]), "r"((b)[1]))

__device__ __forceinline__ void store_pair(float* p, float a, float b) {
    *(float2*)p = make_float2(a, b);
}
__device__ __forceinline__ void store_pair(__half* p, float a, float b) {
    *(__half2*)p = __floats2half2_rn(a, b);
}

// ---------------- prep kernels ---------------------------------------------
__global__ void f2h_kernel(const float* __restrict__ in,
                           __half* __restrict__ out, int n4) {
    for (int i = blockIdx.x * blockDim.x + threadIdx.x; i < n4;
         i += gridDim.x * blockDim.x) {
        float4 v = *(const float4*)(in + (size_t)i * 4);
        __half2 h0 = __floats2half2_rn(v.x, v.y);
        __half2 h1 = __floats2half2_rn(v.z, v.w);
        *(uint2*)(out + (size_t)i * 4) =
            make_uint2(*(uint32_t*)&h0, *(uint32_t*)&h1);
    }
}

// W[K,N] -> Wt[N,K] half. Block (32,8), tile 32x32.
__global__ void transpose_h_kernel(const float* __restrict__ W,
                                   __half* __restrict__ Wt, int K, int N) {
    __shared__ float t[32][33];
    int n0 = blockIdx.x * 32, k0 = blockIdx.y * 32;
    int x = threadIdx.x, y = threadIdx.y;
#pragma unroll
    for (int i = 0; i < 32; i += 8)
        t[y + i][x] = W[(size_t)(k0 + y + i) * N + n0 + x];
    __syncthreads();
#pragma unroll
    for (int i = 0; i < 32; i += 8)
        Wt[(size_t)(n0 + y + i) * K + k0 + x] = __float2half_rn(t[x][y + i]);
}

// ---------------- fp16 mma GEMM --------------------------------------------
// C[M,N] = A[M,K]@Bt[N,K]^T + bias.  CTA 128x128, BK=32 halves, 4-stage
// cp.async pipe, 256 thr (8 warps, 4x2, 32x64 each).  Pitch 40 halves
// (80B) => fragment LDS word = 20*row + tig (mod 32): all-distinct.
#define HBK 32
#define HPH 40
#define HSTAGES 4
#define HTILE (128 * HPH)                   // halves per tile
#define HSTAGE (2 * HTILE)
#define HSMEM_BYTES (HSTAGES * HSTAGE * 2)  // 81920
#define HCHUNKS (KDIM / HBK)                // 32

template <typename OutT>
__global__ __launch_bounds__(256, 2) void gemm_h_kernel(
    const __half* __restrict__ A, const __half* __restrict__ Bt,
    const float* __restrict__ bias, OutT* __restrict__ C, int N)
{
    extern __shared__ __half hsm[];
    const int tid = threadIdx.x;
    const int wid = tid >> 5;
    const int lane = tid & 31;
    const int gid = lane >> 2;
    const int tig = lane & 3;

    const size_t row0 = (size_t)blockIdx.y * 128;
    const size_t col0 = (size_t)blockIdx.x * 128;
    const int wm0 = (wid & 3) * 32;
    const int wn0 = (wid >> 2) * 64;

    const __half* Ab = A  + row0 * KDIM;
    const __half* Bb = Bt + col0 * KDIM;

    float acc[2][8][4];
#pragma unroll
    for (int mt = 0; mt < 2; mt++)
#pragma unroll
        for (int nt = 0; nt < 8; nt++)
#pragma unroll
            for (int j = 0; j < 4; j++) acc[mt][nt][j] = 0.f;

    const uint32_t sbase = smem_u32(hsm);

    auto load_stage = [&](int s, int chunk) {
        const int kof = chunk * HBK;
        uint32_t aS = sbase + (uint32_t)(s * HSTAGE) * 2u;
        uint32_t bS = aS + (uint32_t)HTILE * 2u;
#pragma unroll
        for (int i = 0; i < 2; i++) {
            int idx = tid + i * 256;          // 512 chunks of 16B per matrix
            int r = idx >> 2, ch = idx & 3;
            uint32_t doff = (uint32_t)(r * HPH) * 2u + (uint32_t)ch * 16u;
            CP_ASYNC16(aS + doff, Ab + (size_t)r * KDIM + kof + ch * 8);
            CP_ASYNC16(bS + doff, Bb + (size_t)r * KDIM + kof + ch * 8);
        }
    };

    load_stage(0, 0); CP_COMMIT();
    load_stage(1, 1); CP_COMMIT();
    load_stage(2, 2); CP_COMMIT();

    for (int c = 0; c < HCHUNKS; c++) {
        CP_WAIT2();
        __syncthreads();
        if (c + 3 < HCHUNKS) load_stage((c + 3) & 3, c + 3);
        CP_COMMIT();

        const __half* As = hsm + (c & 3) * HSTAGE;
        const __half* Bs = As + HTILE;
#pragma unroll
        for (int kk = 0; kk < 2; kk++) {
            const int kb = kk * 16;
            uint32_t a[2][4];
#pragma unroll
            for (int mt = 0; mt < 2; mt++) {
                int r = wm0 + mt * 16 + gid;
                a[mt][0] = *(const uint32_t*)&As[(r    ) * HPH + kb + 2 * tig    ];
                a[mt][1] = *(const uint32_t*)&As[(r + 8) * HPH + kb + 2 * tig    ];
                a[mt][2] = *(const uint32_t*)&As[(r    ) * HPH + kb + 2 * tig + 8];
                a[mt][3] = *(const uint32_t*)&As[(r + 8) * HPH + kb + 2 * tig + 8];
            }
            uint32_t b[8][2];
#pragma unroll
            for (int nt = 0; nt < 8; nt++) {
                int n = wn0 + nt * 8 + gid;
                b[nt][0] = *(const uint32_t*)&Bs[n * HPH + kb + 2 * tig    ];
                b[nt][1] = *(const uint32_t*)&Bs[n * HPH + kb + 2 * tig + 8];
            }
#pragma unroll
            for (int mt = 0; mt < 2; mt++)
#pragma unroll
                for (int nt = 0; nt < 8; nt++)
                    MMA_F16(acc[mt][nt], a[mt], b[nt]);
        }
        __syncthreads();
    }

#pragma unroll
    for (int mt = 0; mt < 2; mt++) {
        size_t r = row0 + wm0 + mt * 16 + gid;
#pragma unroll
        for (int nt = 0; nt < 8; nt++) {
            size_t col = col0 + wn0 + nt * 8 + tig * 2;
            float2 bb = *(const float2*)(bias + col);
            store_pair(C + r * N + col, acc[mt][nt][0] + bb.x, acc[mt][nt][1] + bb.y);
            store_pair(C + (r + 8) * N + col, acc[mt][nt][2] + bb.x, acc[mt][nt][3] + bb.y);
        }
    }
}

// ---------------- fp16 tensor-core flash attention -------------------------
// Per CTA: one (b, h, 128-q tile). 8 warps, warp w owns q rows [16w,16w+16).
// Key tiles of 64.  Ks[key][hd], Vt[hd][key] (transposed for B-frag k-
// contiguity), Ps[q][*] (Q staging then per-warp P tiles).  Pitch 72 halves
// (144B) => fragment LDS word = 4*row + tig (mod 32): all-distinct.
#define APH 72

__global__ __launch_bounds__(256, 2) void attn_h_kernel(
    const __half* __restrict__ qkv, __half* __restrict__ y)
{
    __shared__ __half Ks[64 * APH];
    __shared__ __half Vt[64 * APH];
    __shared__ __half Ps[128 * APH];

    const int qb  = gridDim.x - 1 - blockIdx.x;    // big tiles first
    const int bh  = blockIdx.y;
    const int b   = bh >> 4;
    const int h   = bh & 15;
    const int tid = threadIdx.x;
    const int wid = tid >> 5;
    const int lane = tid & 31;
    const int gid = lane >> 2;
    const int tig = lane & 3;
    const int wrow = wid * 16;
    const int q0 = qb * 128;

    const __half* base = qkv + (size_t)b * TSEQ * D3;

    // ---- stage Q (x 1/8, exact in fp16) into Ps; pull fragments ----
    {
        const __half2 s = __float2half2_rn(0.125f);
#pragma unroll
        for (int i = 0; i < 4; i++) {
            int idx = tid + i * 256;               // 1024 uint4 (8 halves each)
            int r = idx >> 3, c8 = (idx & 7) << 3;
            uint4 v = *(const uint4*)(base + (size_t)(q0 + r) * D3 + h * HDIM + c8);
            __half2* h2 = reinterpret_cast<__half2*>(&v);
            h2[0] = __hmul2(h2[0], s); h2[1] = __hmul2(h2[1], s);
            h2[2] = __hmul2(h2[2], s); h2[3] = __hmul2(h2[3], s);
            *(uint4*)&Ps[r * APH + c8] = v;
        }
    }
    __syncthreads();

    uint32_t qf[4][4];
#pragma unroll
    for (int kk = 0; kk < 4; kk++) {
        int kb = kk * 16;
        qf[kk][0] = *(const uint32_t*)&Ps[(wrow + gid    ) * APH + kb + 2 * tig    ];
        qf[kk][1] = *(const uint32_t*)&Ps[(wrow + gid + 8) * APH + kb + 2 * tig    ];
        qf[kk][2] = *(const uint32_t*)&Ps[(wrow + gid    ) * APH + kb + 2 * tig + 8];
        qf[kk][3] = *(const uint32_t*)&Ps[(wrow + gid + 8) * APH + kb + 2 * tig + 8];
    }
    __syncthreads();

    const int r0g = q0 + wrow + gid;
    const int r1g = r0g + 8;

    float m0 = -1e30f, m1 = -1e30f, l0 = 0.f, l1 = 0.f;
    float oacc[8][4];
#pragma unroll
    for (int nt = 0; nt < 8; nt++)
#pragma unroll
        for (int j = 0; j < 4; j++) oacc[nt][j] = 0.f;

    const int ntiles = (qb + 1) * 2;
    for (int t = 0; t < ntiles; t++) {
        const int k0 = t * 64;
        __syncthreads();
        // ---- K tile straight copy: 512 uint4 ----
#pragma unroll
        for (int i = 0; i < 2; i++) {
            int idx = tid + i * 256;
            int r = idx >> 3, c8 = (idx & 7) << 3;
            uint4 v = *(const uint4*)(base + (size_t)(k0 + r) * D3 + DMODEL + h * HDIM + c8);
            *(uint4*)&Ks[r * APH + c8] = v;
        }
        // ---- V tile transposed: warp w handles hd cols [8w,8w+8) ----
        {
            const int c = wid * 8;
#pragma unroll
            for (int rr = 0; rr < 64; rr += 32) {
                int r = rr + lane;
                uint4 v = *(const uint4*)(base + (size_t)(k0 + r) * D3 + 2 * DMODEL + h * HDIM + c);
                const __half* hp = reinterpret_cast<const __half*>(&v);
#pragma unroll
                for (int j = 0; j < 8; j++)
                    Vt[(c + j) * APH + r] = hp[j];
            }
        }
        __syncthreads();

        if (k0 > q0 + wrow + 15) continue;         // warp fully masked

        // ---- S = Q @ K^T ----
        float sacc[8][4];
#pragma unroll
        for (int nt = 0; nt < 8; nt++)
#pragma unroll
            for (int j = 0; j < 4; j++) sacc[nt][j] = 0.f;
#pragma unroll
        for (int kk = 0; kk < 4; kk++) {
            int kb = kk * 16;
            uint32_t bf[8][2];
#pragma unroll
            for (int nt = 0; nt < 8; nt++) {
                int n = nt * 8 + gid;
                bf[nt][0] = *(const uint32_t*)&Ks[n * APH + kb + 2 * tig    ];
                bf[nt][1] = *(const uint32_t*)&Ks[n * APH + kb + 2 * tig + 8];
            }
#pragma unroll
            for (int nt = 0; nt < 8; nt++)
                MMA_F16(sacc[nt], qf[kk], bf[nt]);
        }

        // ---- causal mask + quad row max ----
        float tmax0 = -1e30f, tmax1 = -1e30f;
#pragma unroll
        for (int nt = 0; nt < 8; nt++) {
            int col = k0 + nt * 8 + 2 * tig;
            if (col     > r0g) sacc[nt][0] = -1e30f;
            if (col + 1 > r0g) sacc[nt][1] = -1e30f;
            if (col     > r1g) sacc[nt][2] = -1e30f;
            if (col + 1 > r1g) sacc[nt][3] = -1e30f;
            tmax0 = fmaxf(tmax0, fmaxf(sacc[nt][0], sacc[nt][1]));
            tmax1 = fmaxf(tmax1, fmaxf(sacc[nt][2], sacc[nt][3]));
        }
#pragma unroll
        for (int d = 1; d <= 2; d <<= 1) {
            tmax0 = fmaxf(tmax0, __shfl_xor_sync(0xffffffffu, tmax0, d));
            tmax1 = fmaxf(tmax1, __shfl_xor_sync(0xffffffffu, tmax1, d));
        }

        float mn0 = fmaxf(m0, tmax0), mn1 = fmaxf(m1, tmax1);
        float c0 = __expf(m0 - mn0), c1 = __expf(m1 - mn1);
        l0 *= c0; l1 *= c1; m0 = mn0; m1 = mn1;
#pragma unroll
        for (int nt = 0; nt < 8; nt++) {
            oacc[nt][0] *= c0; oacc[nt][1] *= c0;
            oacc[nt][2] *= c1; oacc[nt][3] *= c1;
        }

        // ---- P = exp(S - m); partial l; store P half2 (warp-private) ----
        __syncwarp();
#pragma unroll
        for (int nt = 0; nt < 8; nt++) {
            float p0 = __expf(sacc[nt][0] - m0);
            float p1 = __expf(sacc[nt][1] - m0);
            float p2 = __expf(sacc[nt][2] - m1);
            float p3 = __expf(sacc[nt][3] - m1);
            l0 += p0 + p1; l1 += p2 + p3;
            int col = nt * 8 + 2 * tig;
            *(__half2*)&Ps[(wrow + gid    ) * APH + col] = __floats2half2_rn(p0, p1);
            *(__half2*)&Ps[(wrow + gid + 8) * APH + col] = __floats2half2_rn(p2, p3);
        }
        __syncwarp();

        // ---- O += P @ V  (B from Vt: k-contiguous) ----
#pragma unroll
        for (int kk = 0; kk < 4; kk++) {
            int kb = kk * 16;
            uint32_t a[4];
            a[0] = *(const uint32_t*)&Ps[(wrow + gid    ) * APH + kb + 2 * tig    ];
            a[1] = *(const uint32_t*)&Ps[(wrow + gid + 8) * APH + kb + 2 * tig    ];
            a[2] = *(const uint32_t*)&Ps[(wrow + gid    ) * APH + kb + 2 * tig + 8];
            a[3] = *(const uint32_t*)&Ps[(wrow + gid + 8) * APH + kb + 2 * tig + 8];
#pragma unroll
            for (int nt = 0; nt < 8; nt++) {
                int n = nt * 8 + gid;
                uint32_t bv[2];
                bv[0] = *(const uint32_t*)&Vt[n * APH + kb + 2 * tig    ];
                bv[1] = *(const uint32_t*)&Vt[n * APH + kb + 2 * tig + 8];
                MMA_F16(oacc[nt], a, bv);
            }
        }
    }

    // ---- quad-reduce partial row sums, normalize, store half y ----
#pragma unroll
    for (int d = 1; d <= 2; d <<= 1) {
        l0 += __shfl_xor_sync(0xffffffffu, l0, d);
        l1 += __shfl_xor_sync(0xffffffffu, l1, d);
    }
    float inv0 = 1.f / l0, inv1 = 1.f / l1;
    __half* y0 = y + (size_t)(b * TSEQ + r0g) * DMODEL + h * HDIM;
    __half* y1 = y + (size_t)(b * TSEQ + r1g) * DMODEL + h * HDIM;
#pragma unroll
    for (int nt = 0; nt < 8; nt++) {
        int col = nt * 8 + 2 * tig;
        *(__half2*)(y0 + col) = __floats2half2_rn(oacc[nt][0] * inv0, oacc[nt][1] * inv0);
        *(__half2*)(y1 + col) = __floats2half2_rn(oacc[nt][2] * inv1, oacc[nt][3] * inv1);
    }
}

// ---------------------------------------------------------------------------
extern "C" void kernel_launch(void* const* d_in, const int* in_sizes, int n_in,
                              void* d_out, int out_size)
{
    (void)in_sizes; (void)n_in; (void)out_size;
    const float* x     = (const float*)d_in[0];
    const float* qkv_w = (const float*)d_in[1];
    const float* qkv_b = (const float*)d_in[2];
    const float* o_w   = (const float*)d_in[3];
    const float* o_b   = (const float*)d_in[4];
    float* out = (float*)d_out;

    __half *xh, *qkvh, *yh, *wqkvt, *wot;
    cudaGetSymbolAddress((void**)&xh, g_xh);
    cudaGetSymbolAddress((void**)&qkvh, g_qkvh);
    cudaGetSymbolAddress((void**)&yh, g_yh);
    cudaGetSymbolAddress((void**)&wqkvt, g_wqkvt);
    cudaGetSymbolAddress((void**)&wot, g_wot);

    cudaFuncSetAttribute(gemm_h_kernel<__half>,
                         cudaFuncAttributeMaxDynamicSharedMemorySize, HSMEM_BYTES);
    cudaFuncSetAttribute(gemm_h_kernel<float>,
                         cudaFuncAttributeMaxDynamicSharedMemorySize, HSMEM_BYTES);

    // prep: fp32 -> fp16 activations; transposed fp16 weights
    f2h_kernel<<<1024, 256>>>(x, xh, MROWS * DMODEL / 4);
    transpose_h_kernel<<<dim3(D3 / 32, DMODEL / 32), dim3(32, 8)>>>(
        qkv_w, wqkvt, DMODEL, D3);
    transpose_h_kernel<<<dim3(DMODEL / 32, DMODEL / 32), dim3(32, 8)>>>(
        o_w, wot, DMODEL, DMODEL);

    // 1) QKV projection -> half
    gemm_h_kernel<__half><<<dim3(D3 / 128, MROWS / 128), 256, HSMEM_BYTES>>>(
        xh, wqkvt, qkv_b, qkvh, D3);

    // 2) causal flash attention (fp16 mma) -> half y
    attn_h_kernel<<<dim3(TSEQ / 128, NBATCH * NHEADS), 256>>>(qkvh, yh);

    // 3) output projection -> fp32 out
    gemm_h_kernel<float><<<dim3(DMODEL / 128, MROWS / 128), 256, HSMEM_BYTES>>>(
        yh, wot, o_b, out, DMODEL);
}

// round 7
// speedup vs baseline: 7.0276x; 1.1744x over previous
#include <cuda_runtime.h>
#include <cuda_fp16.h>
#include <cstdint>
#include <math.h>

#define NBATCH 4
#define TSEQ   2048
#define DMODEL 1024
#define NHEADS 16
#define HDIM   64
#define MROWS  (NBATCH * TSEQ)   // 8192
#define KDIM   DMODEL            // 1024
#define D3     (3 * DMODEL)

// ---------------- scratch (static device globals; no runtime alloc) --------
__device__ __align__(1024) __half g_xh[(size_t)MROWS * DMODEL];        // 16 MB
__device__ __align__(1024) __half g_qkvh[(size_t)MROWS * D3];          // 50 MB
__device__ __align__(1024) __half g_yh[(size_t)MROWS * DMODEL];        // 16 MB
__device__ __align__(1024) __half g_wqkvt[(size_t)D3 * DMODEL];        // 6 MB
__device__ __align__(1024) __half g_wot[(size_t)DMODEL * DMODEL];      // 2 MB

// ---------------- helpers ---------------------------------------------------
#define CP_ASYNC16(dst, src) \
    asm volatile("cp.async.cg.shared.global [%0], [%1], 16;" \
                 :: "r"(dst), "l"(src) : "memory")
#define CP_COMMIT() asm volatile("cp.async.commit_group;" ::: "memory")
#define CP_WAIT2()  asm volatile("cp.async.wait_group 2;" ::: "memory")

__device__ __forceinline__ uint32_t smem_u32(const void* p) {
    uint32_t a;
    asm("{ .reg .u64 t; cvta.to.shared.u64 t, %1; cvt.u32.u64 %0, t; }"
        : "=r"(a) : "l"(p));
    return a;
}

// m16n8k16 fp16 mma, fp32 accum: a:4 b32 regs, b:2, d:4 f32.
#define MMA_F16(d, a, b) \
    asm volatile("mma.sync.aligned.m16n8k16.row.col.f32.f16.f16.f32 " \
        "{%0,%1,%2,%3}, {%4,%5,%6,%7}, {%8,%9}, {%0,%1,%2,%3};" \
        : "+f"((d)[0]), "+f"((d)[1]), "+f"((d)[2]), "+f"((d)[3]) \
        : "r"((a)[0]), "r"((a)[1]), "r"((a)[2]), "r"((a)[3]), \
          "r"((b)[0]), "r"((b)[1]))

#define LDSM_X4(r0, r1, r2, r3, addr) \
    asm volatile("ldmatrix.sync.aligned.m8n8.x4.shared.b16 {%0,%1,%2,%3}, [%4];" \
        : "=r"(r0), "=r"(r1), "=r"(r2), "=r"(r3) : "r"(addr))
#define LDSM_X4_T(r0, r1, r2, r3, addr) \
    asm volatile("ldmatrix.sync.aligned.m8n8.x4.trans.shared.b16 {%0,%1,%2,%3}, [%4];" \
        : "=r"(r0), "=r"(r1), "=r"(r2), "=r"(r3) : "r"(addr))

__device__ __forceinline__ void store_pair(float* p, float a, float b) {
    *(float2*)p = make_float2(a, b);
}
__device__ __forceinline__ void store_pair(__half* p, float a, float b) {
    *(__half2*)p = __floats2half2_rn(a, b);
}

// ---------------- prep kernels ---------------------------------------------
__global__ void f2h_kernel(const float* __restrict__ in,
                           __half* __restrict__ out, int n4) {
    for (int i = blockIdx.x * blockDim.x + threadIdx.x; i < n4;
         i += gridDim.x * blockDim.x) {
        float4 v = *(const float4*)(in + (size_t)i * 4);
        __half2 h0 = __floats2half2_rn(v.x, v.y);
        __half2 h1 = __floats2half2_rn(v.z, v.w);
        *(uint2*)(out + (size_t)i * 4) =
            make_uint2(*(uint32_t*)&h0, *(uint32_t*)&h1);
    }
}

// W[K,N] -> Wt[N,K] half. Block (32,8), tile 32x32.
__global__ void transpose_h_kernel(const float* __restrict__ W,
                                   __half* __restrict__ Wt, int K, int N) {
    __shared__ float t[32][33];
    int n0 = blockIdx.x * 32, k0 = blockIdx.y * 32;
    int x = threadIdx.x, y = threadIdx.y;
#pragma unroll
    for (int i = 0; i < 32; i += 8)
        t[y + i][x] = W[(size_t)(k0 + y + i) * N + n0 + x];
    __syncthreads();
#pragma unroll
    for (int i = 0; i < 32; i += 8)
        Wt[(size_t)(n0 + y + i) * K + k0 + x] = __float2half_rn(t[x][y + i]);
}

// ---------------- fp16 mma GEMM (ldmatrix feed) ----------------------------
// C[M,N] = A[M,K]@Bt[N,K]^T + bias.  CTA 128x128, BK=32 halves, 4-stage
// cp.async, 256 thr (8 warps 4x2, 32x64 each). Pitch 40 halves (80B):
// ldmatrix 8-row groups hit disjoint bank quads (20r mod 32).
#define HBK 32
#define HPH 40
#define HTILE (128 * HPH)
#define HSTAGE (2 * HTILE)
#define HSMEM_BYTES (4 * HSTAGE * 2)  // 81920
#define HCHUNKS (KDIM / HBK)          // 32

template <typename OutT>
__global__ __launch_bounds__(256, 2) void gemm_h_kernel(
    const __half* __restrict__ A, const __half* __restrict__ Bt,
    const float* __restrict__ bias, OutT* __restrict__ C, int N)
{
    extern __shared__ __half hsm[];
    const int tid = threadIdx.x;
    const int wid = tid >> 5;
    const int lane = tid & 31;
    const int gid = lane >> 2;
    const int tig = lane & 3;

    const size_t row0 = (size_t)blockIdx.y * 128;
    const size_t col0 = (size_t)blockIdx.x * 128;
    const int wm0 = (wid & 3) * 32;
    const int wn0 = (wid >> 2) * 64;

    const __half* Ab = A  + row0 * KDIM;
    const __half* Bb = Bt + col0 * KDIM;

    float acc[2][8][4];
#pragma unroll
    for (int mt = 0; mt < 2; mt++)
#pragma unroll
        for (int nt = 0; nt < 8; nt++)
#pragma unroll
            for (int j = 0; j < 4; j++) acc[mt][nt][j] = 0.f;

    const uint32_t sbase = smem_u32(hsm);

    // ldmatrix lane-derived offsets (halves)
    const int aRow = lane & 15, aColSel = (lane >> 4) * 8;          // A pattern
    const int bRow = (lane & 7) + ((lane >> 4) << 3);               // B pattern
    const int bColSel = ((lane >> 3) & 1) * 8;

    auto load_stage = [&](int s, int chunk) {
        const int kof = chunk * HBK;
        uint32_t aS = sbase + (uint32_t)(s * HSTAGE) * 2u;
        uint32_t bS = aS + (uint32_t)HTILE * 2u;
#pragma unroll
        for (int i = 0; i < 2; i++) {
            int idx = tid + i * 256;
            int r = idx >> 2, ch = idx & 3;
            uint32_t doff = (uint32_t)(r * HPH) * 2u + (uint32_t)ch * 16u;
            CP_ASYNC16(aS + doff, Ab + (size_t)r * KDIM + kof + ch * 8);
            CP_ASYNC16(bS + doff, Bb + (size_t)r * KDIM + kof + ch * 8);
        }
    };

    load_stage(0, 0); CP_COMMIT();
    load_stage(1, 1); CP_COMMIT();
    load_stage(2, 2); CP_COMMIT();

    for (int c = 0; c < HCHUNKS; c++) {
        CP_WAIT2();
        __syncthreads();
        if (c + 3 < HCHUNKS) load_stage((c + 3) & 3, c + 3);
        CP_COMMIT();

        const uint32_t aS = sbase + (uint32_t)((c & 3) * HSTAGE) * 2u;
        const uint32_t bS = aS + (uint32_t)HTILE * 2u;
#pragma unroll
        for (int kk = 0; kk < 2; kk++) {
            const int kb = kk * 16;
            uint32_t a[2][4];
#pragma unroll
            for (int mt = 0; mt < 2; mt++) {
                uint32_t ad = aS + (uint32_t)((wm0 + mt * 16 + aRow) * HPH + kb + aColSel) * 2u;
                LDSM_X4(a[mt][0], a[mt][1], a[mt][2], a[mt][3], ad);
            }
            uint32_t b[8][2];
#pragma unroll
            for (int np = 0; np < 4; np++) {
                uint32_t bd = bS + (uint32_t)((wn0 + np * 16 + bRow) * HPH + kb + bColSel) * 2u;
                LDSM_X4(b[2 * np][0], b[2 * np][1], b[2 * np + 1][0], b[2 * np + 1][1], bd);
            }
#pragma unroll
            for (int mt = 0; mt < 2; mt++)
#pragma unroll
                for (int nt = 0; nt < 8; nt++)
                    MMA_F16(acc[mt][nt], a[mt], b[nt]);
        }
        __syncthreads();
    }

#pragma unroll
    for (int mt = 0; mt < 2; mt++) {
        size_t r = row0 + wm0 + mt * 16 + gid;
#pragma unroll
        for (int nt = 0; nt < 8; nt++) {
            size_t col = col0 + wn0 + nt * 8 + tig * 2;
            float2 bb = *(const float2*)(bias + col);
            store_pair(C + r * N + col, acc[mt][nt][0] + bb.x, acc[mt][nt][1] + bb.y);
            store_pair(C + (r + 8) * N + col, acc[mt][nt][2] + bb.x, acc[mt][nt][3] + bb.y);
        }
    }
}

// ---------------- fp16 flash attention (ldmatrix feed) ---------------------
// Per CTA one (b, h, 128-q tile); 8 warps x 16 q-rows; 64-key tiles.
// Ks[key][hd], Vs[key][hd] (V B-frags via ldmatrix.trans), Ps staging.
// Pitch 72 halves (144B): 8-row ldmatrix groups -> banks 4r mod 32, disjoint.
#define APH 72

__global__ __launch_bounds__(256, 2) void attn_h_kernel(
    const __half* __restrict__ qkv, __half* __restrict__ y)
{
    __shared__ __half Ks[64 * APH];
    __shared__ __half Vs[64 * APH];
    __shared__ __half Ps[128 * APH];

    const int qb  = gridDim.x - 1 - blockIdx.x;
    const int bh  = blockIdx.y;
    const int b   = bh >> 4;
    const int h   = bh & 15;
    const int tid = threadIdx.x;
    const int wid = tid >> 5;
    const int lane = tid & 31;
    const int gid = lane >> 2;
    const int tig = lane & 3;
    const int wrow = wid * 16;
    const int q0 = qb * 128;

    const __half* base = qkv + (size_t)b * TSEQ * D3;
    const uint32_t ksS = smem_u32(Ks);
    const uint32_t vsS = smem_u32(Vs);
    const uint32_t psS = smem_u32(Ps);

    const int aRow = lane & 15, aColSel = (lane >> 4) * 8;          // A/Q/P frags
    const int bRow = (lane & 7) + ((lane >> 4) << 3);               // K frags
    const int bColSel = ((lane >> 3) & 1) * 8;
    const int vRow = (lane & 7) + (((lane >> 3) & 1) << 3);         // V trans frags
    const int vColSel = (lane >> 4) * 8;

    // ---- stage Q (x 1/8) into Ps; pull fragments via ldmatrix ----
    {
        const __half2 s = __float2half2_rn(0.125f);
#pragma unroll
        for (int i = 0; i < 4; i++) {
            int idx = tid + i * 256;
            int r = idx >> 3, c8 = (idx & 7) << 3;
            uint4 v = *(const uint4*)(base + (size_t)(q0 + r) * D3 + h * HDIM + c8);
            __half2* h2 = reinterpret_cast<__half2*>(&v);
            h2[0] = __hmul2(h2[0], s); h2[1] = __hmul2(h2[1], s);
            h2[2] = __hmul2(h2[2], s); h2[3] = __hmul2(h2[3], s);
            *(uint4*)&Ps[r * APH + c8] = v;
        }
    }
    __syncthreads();

    uint32_t qf[4][4];
#pragma unroll
    for (int kk = 0; kk < 4; kk++) {
        uint32_t ad = psS + (uint32_t)((wrow + aRow) * APH + kk * 16 + aColSel) * 2u;
        LDSM_X4(qf[kk][0], qf[kk][1], qf[kk][2], qf[kk][3], ad);
    }
    __syncthreads();

    const int r0g = q0 + wrow + gid;
    const int r1g = r0g + 8;

    float m0 = -1e30f, m1 = -1e30f, l0 = 0.f, l1 = 0.f;
    float oacc[8][4];
#pragma unroll
    for (int nt = 0; nt < 8; nt++)
#pragma unroll
        for (int j = 0; j < 4; j++) oacc[nt][j] = 0.f;

    const int ntiles = (qb + 1) * 2;
    for (int t = 0; t < ntiles; t++) {
        const int k0 = t * 64;
        __syncthreads();
        // ---- K/V tiles: straight uint4 copies ----
#pragma unroll
        for (int i = 0; i < 2; i++) {
            int idx = tid + i * 256;
            int r = idx >> 3, c8 = (idx & 7) << 3;
            const __half* kr = base + (size_t)(k0 + r) * D3 + DMODEL + h * HDIM + c8;
            *(uint4*)&Ks[r * APH + c8] = *(const uint4*)kr;
            *(uint4*)&Vs[r * APH + c8] = *(const uint4*)(kr + DMODEL);
        }
        __syncthreads();

        if (k0 > q0 + wrow + 15) continue;         // warp fully masked

        // ---- S = Q @ K^T ----
        float sacc[8][4];
#pragma unroll
        for (int nt = 0; nt < 8; nt++)
#pragma unroll
            for (int j = 0; j < 4; j++) sacc[nt][j] = 0.f;
#pragma unroll
        for (int kk = 0; kk < 4; kk++) {
            const int kb = kk * 16;
            uint32_t bf[8][2];
#pragma unroll
            for (int np = 0; np < 4; np++) {
                uint32_t bd = ksS + (uint32_t)((np * 16 + bRow) * APH + kb + bColSel) * 2u;
                LDSM_X4(bf[2 * np][0], bf[2 * np][1], bf[2 * np + 1][0], bf[2 * np + 1][1], bd);
            }
#pragma unroll
            for (int nt = 0; nt < 8; nt++)
                MMA_F16(sacc[nt], qf[kk], bf[nt]);
        }

        // ---- causal mask + quad row max ----
        float tmax0 = -1e30f, tmax1 = -1e30f;
#pragma unroll
        for (int nt = 0; nt < 8; nt++) {
            int col = k0 + nt * 8 + 2 * tig;
            if (col     > r0g) sacc[nt][0] = -1e30f;
            if (col + 1 > r0g) sacc[nt][1] = -1e30f;
            if (col     > r1g) sacc[nt][2] = -1e30f;
            if (col + 1 > r1g) sacc[nt][3] = -1e30f;
            tmax0 = fmaxf(tmax0, fmaxf(sacc[nt][0], sacc[nt][1]));
            tmax1 = fmaxf(tmax1, fmaxf(sacc[nt][2], sacc[nt][3]));
        }
#pragma unroll
        for (int d = 1; d <= 2; d <<= 1) {
            tmax0 = fmaxf(tmax0, __shfl_xor_sync(0xffffffffu, tmax0, d));
            tmax1 = fmaxf(tmax1, __shfl_xor_sync(0xffffffffu, tmax1, d));
        }

        float mn0 = fmaxf(m0, tmax0), mn1 = fmaxf(m1, tmax1);
        float c0 = __expf(m0 - mn0), c1 = __expf(m1 - mn1);
        l0 *= c0; l1 *= c1; m0 = mn0; m1 = mn1;
#pragma unroll
        for (int nt = 0; nt < 8; nt++) {
            oacc[nt][0] *= c0; oacc[nt][1] *= c0;
            oacc[nt][2] *= c1; oacc[nt][3] *= c1;
        }

        // ---- P = exp(S - m); partial l; store P (warp-private rows) ----
        __syncwarp();
#pragma unroll
        for (int nt = 0; nt < 8; nt++) {
            float p0 = __expf(sacc[nt][0] - m0);
            float p1 = __expf(sacc[nt][1] - m0);
            float p2 = __expf(sacc[nt][2] - m1);
            float p3 = __expf(sacc[nt][3] - m1);
            l0 += p0 + p1; l1 += p2 + p3;
            int col = nt * 8 + 2 * tig;
            *(__half2*)&Ps[(wrow + gid    ) * APH + col] = __floats2half2_rn(p0, p1);
            *(__half2*)&Ps[(wrow + gid + 8) * APH + col] = __floats2half2_rn(p2, p3);
        }
        __syncwarp();

        // ---- O += P @ V  (P via ldmatrix; V via ldmatrix.trans) ----
#pragma unroll
        for (int kk = 0; kk < 4; kk++) {
            const int kb = kk * 16;
            uint32_t a[4];
            {
                uint32_t ad = psS + (uint32_t)((wrow + aRow) * APH + kb + aColSel) * 2u;
                LDSM_X4(a[0], a[1], a[2], a[3], ad);
            }
            uint32_t bv[8][2];
#pragma unroll
            for (int np = 0; np < 4; np++) {
                uint32_t vd = vsS + (uint32_t)((kb + vRow) * APH + np * 16 + vColSel) * 2u;
                LDSM_X4_T(bv[2 * np][0], bv[2 * np][1], bv[2 * np + 1][0], bv[2 * np + 1][1], vd);
            }
#pragma unroll
            for (int nt = 0; nt < 8; nt++)
                MMA_F16(oacc[nt], a, bv[nt]);
        }
    }

    // ---- quad-reduce partial row sums, normalize, store half y ----
#pragma unroll
    for (int d = 1; d <= 2; d <<= 1) {
        l0 += __shfl_xor_sync(0xffffffffu, l0, d);
        l1 += __shfl_xor_sync(0xffffffffu, l1, d);
    }
    float inv0 = 1.f / l0, inv1 = 1.f / l1;
    __half* y0 = y + (size_t)(b * TSEQ + r0g) * DMODEL + h * HDIM;
    __half* y1 = y + (size_t)(b * TSEQ + r1g) * DMODEL + h * HDIM;
#pragma unroll
    for (int nt = 0; nt < 8; nt++) {
        int col = nt * 8 + 2 * tig;
        *(__half2*)(y0 + col) = __floats2half2_rn(oacc[nt][0] * inv0, oacc[nt][1] * inv0);
        *(__half2*)(y1 + col) = __floats2half2_rn(oacc[nt][2] * inv1, oacc[nt][3] * inv1);
    }
}

// ---------------------------------------------------------------------------
extern "C" void kernel_launch(void* const* d_in, const int* in_sizes, int n_in,
                              void* d_out, int out_size)
{
    (void)in_sizes; (void)n_in; (void)out_size;
    const float* x     = (const float*)d_in[0];
    const float* qkv_w = (const float*)d_in[1];
    const float* qkv_b = (const float*)d_in[2];
    const float* o_w   = (const float*)d_in[3];
    const float* o_b   = (const float*)d_in[4];
    float* out = (float*)d_out;

    __half *xh, *qkvh, *yh, *wqkvt, *wot;
    cudaGetSymbolAddress((void**)&xh, g_xh);
    cudaGetSymbolAddress((void**)&qkvh, g_qkvh);
    cudaGetSymbolAddress((void**)&yh, g_yh);
    cudaGetSymbolAddress((void**)&wqkvt, g_wqkvt);
    cudaGetSymbolAddress((void**)&wot, g_wot);

    cudaFuncSetAttribute(gemm_h_kernel<__half>,
                         cudaFuncAttributeMaxDynamicSharedMemorySize, HSMEM_BYTES);
    cudaFuncSetAttribute(gemm_h_kernel<float>,
                         cudaFuncAttributeMaxDynamicSharedMemorySize, HSMEM_BYTES);

    f2h_kernel<<<1024, 256>>>(x, xh, MROWS * DMODEL / 4);
    transpose_h_kernel<<<dim3(D3 / 32, DMODEL / 32), dim3(32, 8)>>>(
        qkv_w, wqkvt, DMODEL, D3);
    transpose_h_kernel<<<dim3(DMODEL / 32, DMODEL / 32), dim3(32, 8)>>>(
        o_w, wot, DMODEL, DMODEL);

    gemm_h_kernel<__half><<<dim3(D3 / 128, MROWS / 128), 256, HSMEM_BYTES>>>(
        xh, wqkvt, qkv_b, qkvh, D3);

    attn_h_kernel<<<dim3(TSEQ / 128, NBATCH * NHEADS), 256>>>(qkvh, yh);

    gemm_h_kernel<float><<<dim3(DMODEL / 128, MROWS / 128), 256, HSMEM_BYTES>>>(
        yh, wot, o_b, out, DMODEL);
}